// round 1
// baseline (speedup 1.0000x reference)
#include <cuda_runtime.h>
#include <cuda_bf16.h>
#include <math.h>

// PolarVoxelizer: zero a [S*Z, A, R] f32 grid (batch 0 only), scatter 1.0f for
// each valid point. searchsorted replicated exactly via binary search on the
// provided bin arrays; radius/z replicated bit-exactly with _rn intrinsics;
// atan2 via atan2f with a double-precision recompute only near bin/FOV
// boundaries.

#define Z_DEPTH   100
#define HALF_FOV  1.134f
#define R_MIN_C   2.7f
#define R_MAX_C   165.0f
#define MAX_RB    512
#define MAX_AB    256

__device__ __forceinline__ int lower_bound_smem(const float* __restrict__ a, int n, float v) {
    int lo = 0, hi = n;
    while (lo < hi) {
        int mid = (lo + hi) >> 1;
        if (a[mid] < v) lo = mid + 1; else hi = mid;
    }
    return lo;  // first index with a[idx] >= v  (searchsorted side='left')
}

__global__ void polar_voxelize_scatter(
    const float* __restrict__ lidars,      // batch-0 points, [S*N, 3]
    const float* __restrict__ r_bins,      // [num_r]
    const float* __restrict__ angle_bins,  // [num_a]
    float* __restrict__ out,               // [S*Z_DEPTH*num_a*num_r]
    int npts, int n_per_s, int num_r, int num_a)
{
    __shared__ float s_r[MAX_RB];
    __shared__ float s_a[MAX_AB];
    for (int i = threadIdx.x; i < num_r; i += blockDim.x) s_r[i] = r_bins[i];
    for (int i = threadIdx.x; i < num_a; i += blockDim.x) s_a[i] = angle_bins[i];
    __syncthreads();

    int i = blockIdx.x * blockDim.x + threadIdx.x;
    if (i >= npts) return;

    float x = lidars[3 * i + 0];
    float y = lidars[3 * i + 1];
    float z = lidars[3 * i + 2];

    // radius: bit-exact vs XLA f32 (no FMA contraction, IEEE sqrt)
    float xx = __fmul_rn(x, x);
    float yy = __fmul_rn(y, y);
    float radius = __fsqrt_rn(__fadd_rn(xx, yy));
    if (!(radius < R_MAX_C) || !(radius > R_MIN_C)) return;

    // angle: fast path atan2f; refine in double only near decision boundaries
    float v = atan2f(y, x);
    float eps = fmaxf(fabsf(v) * 1.0e-6f, 1.0e-7f);

    int yg = lower_bound_smem(s_a, num_a, v);
    bool near = (fabsf(fabsf(v) - HALF_FOV) <= eps);
    if (yg < num_a && fabsf(v - s_a[yg])     <= eps) near = true;
    if (yg > 0     && fabsf(v - s_a[yg - 1]) <= eps) near = true;
    if (near) {
        v = (float)atan2((double)y, (double)x);   // ~correctly-rounded f32
        yg = lower_bound_smem(s_a, num_a, v);
    }
    if (!(fabsf(v) < HALF_FOV)) return;

    int xg = lower_bound_smem(s_r, num_r, radius);

    // zg: bit-exact (z - (-2.0)) / 0.2 then floor
    int zg = (int)floorf(__fdiv_rn(__fsub_rn(z, -2.0f), 0.2f));

    int s = i / n_per_s;  // scene index within batch 0
    int lin = ((s * Z_DEPTH + zg) * num_a + yg) * num_r + xg;
    out[lin] = 1.0f;  // .set(1.0): constant store, race-free
}

extern "C" void kernel_launch(void* const* d_in, const int* in_sizes, int n_in,
                              void* d_out, int out_size) {
    const float* lidars     = (const float*)d_in[0];
    const float* r_bins     = (const float*)d_in[1];
    const float* angle_bins = (const float*)d_in[2];
    float* out = (float*)d_out;

    const int B = 2;  // output takes only batch 0; batch-1 points never land in it
    int num_r = in_sizes[1];
    int num_a = in_sizes[2];
    int npts  = in_sizes[0] / (3 * B);                 // S*N batch-0 points
    int S     = out_size / (Z_DEPTH * num_a * num_r);  // scenes
    int n_per_s = npts / S;

    cudaMemsetAsync(out, 0, (size_t)out_size * sizeof(float), 0);

    int threads = 256;
    int blocks = (npts + threads - 1) / threads;
    polar_voxelize_scatter<<<blocks, threads>>>(
        lidars, r_bins, angle_bins, out, npts, n_per_s, num_r, num_a);
}

// round 2
// speedup vs baseline: 1.0906x; 1.0906x over previous
#include <cuda_runtime.h>
#include <cuda_bf16.h>
#include <math.h>

// PolarVoxelizer R2: analytic bin-index guess (uniform angle bins, geometric
// r bins) + exact lower_bound fixup against the real bin arrays in smem.
// 4 points per thread via float4 loads. memset + scatter of 1.0f.

#define Z_DEPTH   100
#define HALF_FOV  1.134f
#define R_MIN_C   2.7f
#define R_MAX_C   165.0f
#define MAX_RB    512
#define MAX_AB    256

// Exact searchsorted(side='left') given an approximate starting index.
__device__ __forceinline__ int lb_fixup(const float* __restrict__ a, int n, float v, int idx) {
    idx = min(max(idx, 0), n);
    while (idx > 0 && a[idx - 1] >= v) --idx;
    while (idx < n && a[idx] < v) ++idx;
    return idx;
}

__global__ void polar_voxelize_scatter(
    const float4* __restrict__ lidars4,    // batch-0 points as float4 stream
    const float* __restrict__ r_bins,      // [num_r]
    const float* __restrict__ angle_bins,  // [num_a]
    float* __restrict__ out,               // [S*Z_DEPTH*num_a*num_r]
    int npts, int n_per_s, int num_r, int num_a,
    float a0, float inv_astep,             // angle: uniform-grid params
    float log2_rmin, float inv_log2_1pd)   // radius: geometric-grid params
{
    __shared__ float s_r[MAX_RB];
    __shared__ float s_a[MAX_AB];
    for (int i = threadIdx.x; i < num_r; i += blockDim.x) s_r[i] = r_bins[i];
    for (int i = threadIdx.x; i < num_a; i += blockDim.x) s_a[i] = angle_bins[i];
    __syncthreads();

    int base = (blockIdx.x * blockDim.x + threadIdx.x) * 4;  // first point of this thread
    if (base >= npts) return;

    // 4 points = 12 floats = 3 float4 loads (perfectly coalesced)
    int v4 = base * 3 / 4;  // base is multiple of 4 -> v4 = 3*base/4
    float4 q0 = lidars4[v4 + 0];
    float4 q1 = lidars4[v4 + 1];
    float4 q2 = lidars4[v4 + 2];
    float px[4] = {q0.x, q0.w, q1.z, q2.y};
    float py[4] = {q0.y, q1.x, q1.w, q2.z};
    float pz[4] = {q0.z, q1.y, q2.x, q2.w};

    #pragma unroll
    for (int k = 0; k < 4; ++k) {
        int i = base + k;
        if (i >= npts) return;
        float x = px[k], y = py[k], z = pz[k];

        // radius: bit-exact vs XLA f32 (no FMA contraction, IEEE sqrt)
        float radius = __fsqrt_rn(__fadd_rn(__fmul_rn(x, x), __fmul_rn(y, y)));
        if (!(radius < R_MAX_C) || !(radius > R_MIN_C)) continue;

        // angle: atan2f fast path, double recompute only near decision boundaries
        float v = atan2f(y, x);
        float eps = fmaxf(fabsf(v) * 1.0e-6f, 1.0e-7f);

        int yg0 = (int)floorf((v - a0) * inv_astep);
        int yg = lb_fixup(s_a, num_a, v, yg0);

        bool near = (fabsf(fabsf(v) - HALF_FOV) <= eps);
        if (yg < num_a && fabsf(v - s_a[yg])     <= eps) near = true;
        if (yg > 0     && fabsf(v - s_a[yg - 1]) <= eps) near = true;
        if (near) {
            v = (float)atan2((double)y, (double)x);  // ~correctly-rounded f32
            yg = lb_fixup(s_a, num_a, v, yg);
        }
        if (!(fabsf(v) < HALF_FOV)) continue;

        // radius bin: geometric guess + exact fixup
        int xg0 = (int)floorf((__log2f(radius) - log2_rmin) * inv_log2_1pd);
        int xg = lb_fixup(s_r, num_r, radius, xg0);

        // zg: bit-exact (z - (-2.0)) / 0.2 then floor
        int zg = (int)floorf(__fdiv_rn(__fsub_rn(z, -2.0f), 0.2f));

        int s = i / n_per_s;  // scene index within batch 0
        int lin = ((s * Z_DEPTH + zg) * num_a + yg) * num_r + xg;
        out[lin] = 1.0f;  // .set(1.0): constant store, race-free
    }
}

extern "C" void kernel_launch(void* const* d_in, const int* in_sizes, int n_in,
                              void* d_out, int out_size) {
    const float* lidars     = (const float*)d_in[0];
    const float* r_bins     = (const float*)d_in[1];
    const float* angle_bins = (const float*)d_in[2];
    float* out = (float*)d_out;

    const int B = 2;  // output keeps only batch 0
    int num_r = in_sizes[1];
    int num_a = in_sizes[2];
    int npts  = in_sizes[0] / (3 * B);                 // S*N batch-0 points
    int S     = out_size / (Z_DEPTH * num_a * num_r);
    int n_per_s = npts / S;

    // Analytic grid params (guesses only; exactness comes from lb_fixup)
    double fov = 2.268;
    float a0 = (float)(-fov / 2.0);
    float inv_astep = (float)((num_a - 1) / fov);
    double delta = pow((165.0 + 0.0001) / 2.7, 1.0 / (double)(num_r - 1)) - 1.0;
    float log2_rmin = (float)(log(2.7) / log(2.0));
    float inv_log2_1pd = (float)(log(2.0) / log(1.0 + delta));

    cudaMemsetAsync(out, 0, (size_t)out_size * sizeof(float), 0);

    int threads = 256;
    int pts_per_block = threads * 4;
    int blocks = (npts + pts_per_block - 1) / pts_per_block;
    polar_voxelize_scatter<<<blocks, threads>>>(
        (const float4*)lidars, r_bins, angle_bins, out,
        npts, n_per_s, num_r, num_a,
        a0, inv_astep, log2_rmin, inv_log2_1pd);
}